// round 1
// baseline (speedup 1.0000x reference)
#include <cuda_runtime.h>
#include <math.h>
#include <stdint.h>

// ---------------- dimensions ----------------
#define TOKENS 4096      // B*S = 2*2048
#define SEQLEN 2048
#define NB 2
#define DM 2048
#define NH 16
#define QLORA 1536
#define KVLORA 512
#define NOPE 128
#define ROPE 64
#define DQK 192
#define DV 128
#define DFF 8192

// ---------------- scratch (device globals: allocation-free) ----------------
__device__ float g_h[TOKENS * DM];
__device__ float g_qlat[TOKENS * QLORA];
__device__ float g_q[TOKENS * NH * DQK];     // raw q from GEMM: [t][h][nope128,rope64]
__device__ float g_Q[TOKENS * NH * DQK];     // rope-applied: [t][h][rope64,nope128]
__device__ float g_kvlr[TOKENS * (KVLORA + ROPE)];
__device__ float g_kvnorm[TOKENS * KVLORA];
__device__ float g_kv[TOKENS * NH * (NOPE + DV)];   // [t][ knope(2048) | v(2048) ]
__device__ float g_krope[TOKENS * ROPE];
__device__ float g_K[TOKENS * NH * DQK];     // [t][h][rope64,nope128]
__device__ float g_attn[TOKENS * NH * DV];   // [t][h*128+c]
__device__ float g_x[TOKENS * DM];
__device__ float g_h2[TOKENS * DM];
__device__ float g_gate[TOKENS * DFF];
__device__ float g_up[TOKENS * DFF];
__device__ float g_ff[TOKENS * DFF];

// ---------------- RMSNorm (one block per row) ----------------
__global__ void rmsnorm_kernel(const float* __restrict__ in, const float* __restrict__ w,
                               float* __restrict__ out, int cols, int in_ld, int out_ld) {
    int row = blockIdx.x;
    const float* x = in + (size_t)row * in_ld;
    float* y = out + (size_t)row * out_ld;
    float ss = 0.f;
    for (int c = threadIdx.x; c < cols; c += blockDim.x) {
        float v = x[c];
        ss += v * v;
    }
    __shared__ float red[256];
    red[threadIdx.x] = ss;
    __syncthreads();
    for (int s = 128; s > 0; s >>= 1) {
        if (threadIdx.x < s) red[threadIdx.x] += red[threadIdx.x + s];
        __syncthreads();
    }
    float scale = 1.0f / sqrtf(red[0] / (float)cols + 1e-5f);
    for (int c = threadIdx.x; c < cols; c += blockDim.x) {
        float v = x[c] * scale;
        if (w) v *= w[c];
        y[c] = v;
    }
}

// ---------------- SGEMM: C[M,N] = A[M,K] @ B[K,N] (+ D) ----------------
// BM=128, BN=128, BK=16, 256 threads, 8x8 per thread.
// Requirements: M % 128 == 0, K % 16 == 0, N % 4 == 0 (N tiles guarded).
__global__ __launch_bounds__(256) void sgemm128(
    const float* __restrict__ A, const float* __restrict__ B,
    const float* __restrict__ D, float* __restrict__ C,
    int M, int N, int K) {
    __shared__ __align__(16) float As[16][132];  // transposed: As[k][m]
    __shared__ __align__(16) float Bs[16][132];

    const int tid = threadIdx.x;
    const int tx = tid & 15;
    const int ty = tid >> 4;
    const int row0 = blockIdx.y * 128;
    const int col0 = blockIdx.x * 128;

    float acc[8][8];
#pragma unroll
    for (int i = 0; i < 8; i++)
#pragma unroll
        for (int j = 0; j < 8; j++) acc[i][j] = 0.f;

    for (int k0 = 0; k0 < K; k0 += 16) {
        // load A tile (128x16) transposed into As[k][m]
#pragma unroll
        for (int f = tid; f < 512; f += 256) {
            int r = f >> 2;
            int c4 = (f & 3) * 4;
            float4 v = *(const float4*)(A + (size_t)(row0 + r) * K + k0 + c4);
            As[c4 + 0][r] = v.x;
            As[c4 + 1][r] = v.y;
            As[c4 + 2][r] = v.z;
            As[c4 + 3][r] = v.w;
        }
        // load B tile (16x128)
#pragma unroll
        for (int f = tid; f < 512; f += 256) {
            int r = f >> 5;
            int c4 = (f & 31) * 4;
            int col = col0 + c4;
            float4 v = make_float4(0.f, 0.f, 0.f, 0.f);
            if (col < N) v = *(const float4*)(B + (size_t)(k0 + r) * N + col);
            *(float4*)&Bs[r][c4] = v;
        }
        __syncthreads();

#pragma unroll
        for (int kk = 0; kk < 16; kk++) {
            float4 a0 = *(const float4*)&As[kk][ty * 8];
            float4 a1 = *(const float4*)&As[kk][ty * 8 + 4];
            float4 b0 = *(const float4*)&Bs[kk][tx * 8];
            float4 b1 = *(const float4*)&Bs[kk][tx * 8 + 4];
            float a[8] = {a0.x, a0.y, a0.z, a0.w, a1.x, a1.y, a1.z, a1.w};
            float b[8] = {b0.x, b0.y, b0.z, b0.w, b1.x, b1.y, b1.z, b1.w};
#pragma unroll
            for (int i = 0; i < 8; i++)
#pragma unroll
                for (int j = 0; j < 8; j++) acc[i][j] = fmaf(a[i], b[j], acc[i][j]);
        }
        __syncthreads();
    }

#pragma unroll
    for (int i = 0; i < 8; i++) {
        int r = row0 + ty * 8 + i;
#pragma unroll
        for (int j = 0; j < 8; j++) {
            int c = col0 + tx * 8 + j;
            if (c < N) {
                float v = acc[i][j];
                if (D) v += D[(size_t)r * N + c];
                C[(size_t)r * N + c] = v;
            }
        }
    }
}

// ---------------- RoPE for Q + layout reorder to [rope,nope] ----------------
__global__ void rope_q_kernel(const float* __restrict__ qin,
                              const float* __restrict__ cosT, const float* __restrict__ sinT,
                              float* __restrict__ qout) {
    int t = blockIdx.x;
    int h = blockIdx.y;
    int s = t & (SEQLEN - 1);
    const float* in = qin + (size_t)t * (NH * DQK) + h * DQK;   // [nope128 | rope64]
    float* out = qout + (size_t)t * (NH * DQK) + h * DQK;       // [rope64 | nope128]
    int tid = threadIdx.x;
    if (tid < 32) {
        float xr = in[NOPE + 2 * tid];
        float xi = in[NOPE + 2 * tid + 1];
        float c = cosT[(size_t)s * 32 + tid];
        float sn = sinT[(size_t)s * 32 + tid];
        out[2 * tid] = xr * c - xi * sn;
        out[2 * tid + 1] = xr * sn + xi * c;
    }
    // copy nope (128 threads)
    out[ROPE + tid] = in[tid];
}

// ---------------- RoPE for K-rope (per token, shared across heads) ----------------
__global__ void rope_k_kernel(const float* __restrict__ kvlr,
                              const float* __restrict__ cosT, const float* __restrict__ sinT,
                              float* __restrict__ krope) {
    int t = blockIdx.x;
    int s = t & (SEQLEN - 1);
    int j = threadIdx.x;  // 32
    const float* in = kvlr + (size_t)t * (KVLORA + ROPE) + KVLORA;
    float xr = in[2 * j];
    float xi = in[2 * j + 1];
    float c = cosT[(size_t)s * 32 + j];
    float sn = sinT[(size_t)s * 32 + j];
    krope[(size_t)t * ROPE + 2 * j] = xr * c - xi * sn;
    krope[(size_t)t * ROPE + 2 * j + 1] = xr * sn + xi * c;
}

// ---------------- assemble K = [rope64 (bcast) | knope128] per (t,h) ----------------
__global__ void assemble_k_kernel(const float* __restrict__ krope, const float* __restrict__ kv,
                                  float* __restrict__ K) {
    int t = blockIdx.x;
    int h = blockIdx.y;
    int d = threadIdx.x;  // 192
    float v;
    if (d < ROPE)
        v = krope[(size_t)t * ROPE + d];
    else
        v = kv[(size_t)t * (NH * (NOPE + DV)) + h * NOPE + (d - ROPE)];
    K[(size_t)t * (NH * DQK) + h * DQK + d] = v;
}

// ---------------- flash attention (fp32, 64x64 tiles, online softmax) ----------------
#define ATT_QK_PAD 68
#define ATT_SMEM_FLOATS (192 * ATT_QK_PAD * 2 + 64 * 128 + 64 * 65 + 192)
#define ATT_SMEM_BYTES (ATT_SMEM_FLOATS * 4)

__global__ __launch_bounds__(256) void attn_kernel(
    const float* __restrict__ Q, const float* __restrict__ K,
    const float* __restrict__ KV, const int* __restrict__ seqmask,
    float* __restrict__ O) {
    extern __shared__ float smf[];
    float* QsT = smf;                          // [192][68]
    float* KsT = QsT + 192 * ATT_QK_PAD;       // [192][68]
    float* Vs = KsT + 192 * ATT_QK_PAD;        // [64][128]
    float* Ss = Vs + 64 * 128;                 // [64][65]
    float* mrow = Ss + 64 * 65;                // [64]
    float* lrow = mrow + 64;                   // [64]
    float* crow = lrow + 64;                   // [64]

    const int tid = threadIdx.x;
    const int qt = gridDim.x - 1 - blockIdx.x;  // reversed for load balance
    const int h = blockIdx.y;
    const int b = blockIdx.z;
    const int ty = tid >> 4, tx = tid & 15;
    const int r0 = ty * 4, c0 = tx * 4, cc0 = tx * 8;
    const float scale = 0.07216878364870323f;  // 1/sqrt(192)

    const float* Qb = Q + ((size_t)(b * SEQLEN + qt * 64) * NH + h) * DQK;
    for (int idx = tid; idx < 64 * 192; idx += 256) {
        int r = idx / 192, d = idx - r * 192;
        QsT[d * ATT_QK_PAD + r] = Qb[(size_t)r * (NH * DQK) + d];
    }
    if (tid < 64) {
        mrow[tid] = -INFINITY;
        lrow[tid] = 0.f;
    }
    float acc[4][8];
#pragma unroll
    for (int i = 0; i < 4; i++)
#pragma unroll
        for (int j = 0; j < 8; j++) acc[i][j] = 0.f;
    __syncthreads();

    for (int kt = 0; kt <= qt; kt++) {
        const float* Kb = K + ((size_t)(b * SEQLEN + kt * 64) * NH + h) * DQK;
        for (int idx = tid; idx < 64 * 192; idx += 256) {
            int r = idx / 192, d = idx - r * 192;
            KsT[d * ATT_QK_PAD + r] = Kb[(size_t)r * (NH * DQK) + d];
        }
        const float* Vb = KV + (size_t)(b * SEQLEN + kt * 64) * (NH * (NOPE + DV)) + NH * NOPE + h * DV;
        for (int idx = tid; idx < 64 * 128; idx += 256) {
            int r = idx >> 7, c = idx & 127;
            Vs[idx] = Vb[(size_t)r * (NH * (NOPE + DV)) + c];
        }
        __syncthreads();

        float s[4][4];
#pragma unroll
        for (int i = 0; i < 4; i++)
#pragma unroll
            for (int j = 0; j < 4; j++) s[i][j] = 0.f;

#pragma unroll 4
        for (int d = 0; d < 192; d++) {
            float4 qv = *(const float4*)&QsT[d * ATT_QK_PAD + r0];
            float4 kv4 = *(const float4*)&KsT[d * ATT_QK_PAD + c0];
            float qa[4] = {qv.x, qv.y, qv.z, qv.w};
            float ka[4] = {kv4.x, kv4.y, kv4.z, kv4.w};
#pragma unroll
            for (int i = 0; i < 4; i++)
#pragma unroll
                for (int j = 0; j < 4; j++) s[i][j] = fmaf(qa[i], ka[j], s[i][j]);
        }
        // mask + store scores
#pragma unroll
        for (int j = 0; j < 4; j++) {
            int kg = kt * 64 + c0 + j;
            bool ok = seqmask[b * SEQLEN + kg] > 0;
#pragma unroll
            for (int i = 0; i < 4; i++) {
                int qg = qt * 64 + r0 + i;
                float v = s[i][j] * scale;
                if (kg > qg || !ok) v = -1e30f;
                Ss[(r0 + i) * 65 + c0 + j] = v;
            }
        }
        __syncthreads();

        if (tid < 64) {
            int r = tid;
            float mold = mrow[r];
            float mx = mold;
            for (int j = 0; j < 64; j++) mx = fmaxf(mx, Ss[r * 65 + j]);
            float corr = expf(mold - mx);
            float sum = 0.f;
            for (int j = 0; j < 64; j++) {
                float p = expf(Ss[r * 65 + j] - mx);
                Ss[r * 65 + j] = p;
                sum += p;
            }
            lrow[r] = lrow[r] * corr + sum;
            mrow[r] = mx;
            crow[r] = corr;
        }
        __syncthreads();

        float cf[4];
#pragma unroll
        for (int i = 0; i < 4; i++) cf[i] = crow[r0 + i];
#pragma unroll
        for (int i = 0; i < 4; i++)
#pragma unroll
            for (int j = 0; j < 8; j++) acc[i][j] *= cf[i];

        for (int k = 0; k < 64; k++) {
            float p[4];
#pragma unroll
            for (int i = 0; i < 4; i++) p[i] = Ss[(r0 + i) * 65 + k];
            float4 v0 = *(const float4*)&Vs[k * 128 + cc0];
            float4 v1 = *(const float4*)&Vs[k * 128 + cc0 + 4];
            float vv[8] = {v0.x, v0.y, v0.z, v0.w, v1.x, v1.y, v1.z, v1.w};
#pragma unroll
            for (int i = 0; i < 4; i++)
#pragma unroll
                for (int j = 0; j < 8; j++) acc[i][j] = fmaf(p[i], vv[j], acc[i][j]);
        }
        __syncthreads();
    }

    float inv[4];
#pragma unroll
    for (int i = 0; i < 4; i++) inv[i] = 1.f / lrow[r0 + i];
#pragma unroll
    for (int i = 0; i < 4; i++) {
        size_t base = (size_t)(b * SEQLEN + qt * 64 + r0 + i) * (NH * DV) + h * DV + cc0;
#pragma unroll
        for (int j = 0; j < 8; j++) O[base + j] = acc[i][j] * inv[i];
    }
}

// ---------------- silu(gate) * up ----------------
__global__ void silu_mul_kernel(const float* __restrict__ g, const float* __restrict__ u,
                                float* __restrict__ ff, int n) {
    for (int i = blockIdx.x * blockDim.x + threadIdx.x; i < n; i += gridDim.x * blockDim.x) {
        float x = g[i];
        ff[i] = (x / (1.f + expf(-x))) * u[i];
    }
}

// ---------------- launch ----------------
extern "C" void kernel_launch(void* const* d_in, const int* in_sizes, int n_in,
                              void* d_out, int out_size) {
    const float* hidden = (const float*)d_in[0];
    const int* seqmask = (const int*)d_in[1];
    const float* cosT = (const float*)d_in[2];
    const float* sinT = (const float*)d_in[3];
    const float* ln1 = (const float*)d_in[4];
    const float* ln2 = (const float*)d_in[5];
    const float* Wq_down = (const float*)d_in[6];
    const float* Wq_up = (const float*)d_in[7];
    const float* Wkv_down = (const float*)d_in[8];
    const float* Wkv_up = (const float*)d_in[9];
    const float* Wo = (const float*)d_in[10];
    const float* Wgate = (const float*)d_in[11];
    const float* Wup = (const float*)d_in[12];
    const float* Wdown = (const float*)d_in[13];
    float* out = (float*)d_out;

    float *p_h, *p_qlat, *p_q, *p_Q, *p_kvlr, *p_kvnorm, *p_kv, *p_krope, *p_K;
    float *p_attn, *p_x, *p_h2, *p_gate, *p_up, *p_ff;
    cudaGetSymbolAddress((void**)&p_h, g_h);
    cudaGetSymbolAddress((void**)&p_qlat, g_qlat);
    cudaGetSymbolAddress((void**)&p_q, g_q);
    cudaGetSymbolAddress((void**)&p_Q, g_Q);
    cudaGetSymbolAddress((void**)&p_kvlr, g_kvlr);
    cudaGetSymbolAddress((void**)&p_kvnorm, g_kvnorm);
    cudaGetSymbolAddress((void**)&p_kv, g_kv);
    cudaGetSymbolAddress((void**)&p_krope, g_krope);
    cudaGetSymbolAddress((void**)&p_K, g_K);
    cudaGetSymbolAddress((void**)&p_attn, g_attn);
    cudaGetSymbolAddress((void**)&p_x, g_x);
    cudaGetSymbolAddress((void**)&p_h2, g_h2);
    cudaGetSymbolAddress((void**)&p_gate, g_gate);
    cudaGetSymbolAddress((void**)&p_up, g_up);
    cudaGetSymbolAddress((void**)&p_ff, g_ff);

    // 1. h = rmsnorm(hidden) * ln1_w
    rmsnorm_kernel<<<TOKENS, 256>>>(hidden, ln1, p_h, DM, DM, DM);

    // 2. q_latent = rmsnorm(h @ Wq_down)
    sgemm128<<<dim3(QLORA / 128, TOKENS / 128), 256>>>(p_h, Wq_down, nullptr, p_qlat, TOKENS, QLORA, DM);
    rmsnorm_kernel<<<TOKENS, 256>>>(p_qlat, nullptr, p_qlat, QLORA, QLORA, QLORA);

    // 3. q = q_latent @ Wq_up ; rope + reorder
    sgemm128<<<dim3((NH * DQK) / 128, TOKENS / 128), 256>>>(p_qlat, Wq_up, nullptr, p_q, TOKENS, NH * DQK, QLORA);
    rope_q_kernel<<<dim3(TOKENS, NH), 128>>>(p_q, cosT, sinT, p_Q);

    // 4. kv_lr = h @ Wkv_down ; split + rope(k_rope) + rmsnorm(kv_latent)
    sgemm128<<<dim3((KVLORA + ROPE + 127) / 128, TOKENS / 128), 256>>>(p_h, Wkv_down, nullptr, p_kvlr,
                                                                       TOKENS, KVLORA + ROPE, DM);
    rope_k_kernel<<<TOKENS, 32>>>(p_kvlr, cosT, sinT, p_krope);
    rmsnorm_kernel<<<TOKENS, 256>>>(p_kvlr, nullptr, p_kvnorm, KVLORA, KVLORA + ROPE, KVLORA);

    // 5. kv = kvnorm @ Wkv_up ; assemble K
    sgemm128<<<dim3((NH * (NOPE + DV)) / 128, TOKENS / 128), 256>>>(p_kvnorm, Wkv_up, nullptr, p_kv,
                                                                    TOKENS, NH * (NOPE + DV), KVLORA);
    assemble_k_kernel<<<dim3(TOKENS, NH), 192>>>(p_krope, p_kv, p_K);

    // 6. attention
    cudaFuncSetAttribute(attn_kernel, cudaFuncAttributeMaxDynamicSharedMemorySize, ATT_SMEM_BYTES);
    attn_kernel<<<dim3(SEQLEN / 64, NH, NB), 256, ATT_SMEM_BYTES>>>(p_Q, p_K, p_kv, seqmask, p_attn);

    // 7. x = residual + attn @ Wo
    sgemm128<<<dim3(DM / 128, TOKENS / 128), 256>>>(p_attn, Wo, hidden, p_x, TOKENS, DM, NH * DV);

    // 8. h2 = rmsnorm(x) * ln2_w
    rmsnorm_kernel<<<TOKENS, 256>>>(p_x, ln2, p_h2, DM, DM, DM);

    // 9. MLP
    sgemm128<<<dim3(DFF / 128, TOKENS / 128), 256>>>(p_h2, Wgate, nullptr, p_gate, TOKENS, DFF, DM);
    sgemm128<<<dim3(DFF / 128, TOKENS / 128), 256>>>(p_h2, Wup, nullptr, p_up, TOKENS, DFF, DM);
    silu_mul_kernel<<<4096, 256>>>(p_gate, p_up, p_ff, TOKENS * DFF);

    // 10. out = x + ff @ Wdown
    sgemm128<<<dim3(DM / 128, TOKENS / 128), 256>>>(p_ff, Wdown, p_x, out, TOKENS, DM, DFF);
}

// round 3
// speedup vs baseline: 1.7822x; 1.7822x over previous
#include <cuda_runtime.h>
#include <cuda_bf16.h>
#include <math.h>
#include <stdint.h>

// ---------------- dimensions ----------------
#define TOKENS 4096
#define SEQLEN 2048
#define NB 2
#define DM 2048
#define NH 16
#define QLORA 1536
#define KVLORA 512
#define NOPE 128
#define ROPE 64
#define DQK 192
#define DV 128
#define DFF 8192

typedef __nv_bfloat16 bf16;

// ---------------- fp32 scratch ----------------
__device__ float g_qlat[TOKENS * QLORA];
__device__ float g_q[TOKENS * NH * DQK];
__device__ float g_Q[TOKENS * NH * DQK];
__device__ float g_kvlr[TOKENS * (KVLORA + ROPE)];
__device__ float g_kv[TOKENS * NH * (NOPE + DV)];
__device__ float g_krope[TOKENS * ROPE];
__device__ float g_K[TOKENS * NH * DQK];
__device__ float g_x[TOKENS * DM];
__device__ float g_gate[TOKENS * DFF];
__device__ float g_up[TOKENS * DFF];

// ---------------- bf16 hi/lo activations ----------------
__device__ bf16 g_h_h[TOKENS * DM];
__device__ bf16 g_h_l[TOKENS * DM];
__device__ bf16 g_qln_h[TOKENS * QLORA];
__device__ bf16 g_qln_l[TOKENS * QLORA];
__device__ bf16 g_kvn_h[TOKENS * KVLORA];
__device__ bf16 g_kvn_l[TOKENS * KVLORA];
__device__ bf16 g_at_h[TOKENS * NH * DV];
__device__ bf16 g_at_l[TOKENS * NH * DV];
__device__ bf16 g_h2_h[TOKENS * DM];
__device__ bf16 g_h2_l[TOKENS * DM];
__device__ bf16 g_ff_h[TOKENS * DFF];
__device__ bf16 g_ff_l[TOKENS * DFF];

// ---------------- bf16 hi/lo transposed weights [N][K] ----------------
__device__ bf16 g_wqd_h[QLORA * DM];
__device__ bf16 g_wqd_l[QLORA * DM];
__device__ bf16 g_wqu_h[(NH * DQK) * QLORA];
__device__ bf16 g_wqu_l[(NH * DQK) * QLORA];
__device__ bf16 g_wkvd_h[(KVLORA + ROPE) * DM];
__device__ bf16 g_wkvd_l[(KVLORA + ROPE) * DM];
__device__ bf16 g_wkvu_h[(NH * (NOPE + DV)) * KVLORA];
__device__ bf16 g_wkvu_l[(NH * (NOPE + DV)) * KVLORA];
__device__ bf16 g_wo_h[DM * (NH * DV)];
__device__ bf16 g_wo_l[DM * (NH * DV)];
__device__ bf16 g_wg_h[DFF * DM];
__device__ bf16 g_wg_l[DFF * DM];
__device__ bf16 g_wu_h[DFF * DM];
__device__ bf16 g_wu_l[DFF * DM];
__device__ bf16 g_wd_h[DM * DFF];
__device__ bf16 g_wd_l[DM * DFF];

// ==================== PTX helpers (generic sm_80+ features only) ====================
__device__ __forceinline__ uint32_t smem_u32(const void* p) {
    uint32_t a;
    asm("{ .reg .u64 t; cvta.to.shared.u64 t, %1; cvt.u32.u64 %0, t; }" : "=r"(a) : "l"(p));
    return a;
}
__device__ __forceinline__ void cp16(uint32_t d, const void* s, int sz) {
    asm volatile("cp.async.cg.shared.global [%0], [%1], 16, %2;"
                 :: "r"(d), "l"(s), "r"(sz) : "memory");
}
__device__ __forceinline__ void cp_commit() {
    asm volatile("cp.async.commit_group;" ::: "memory");
}
__device__ __forceinline__ void cp_wait0() {
    asm volatile("cp.async.wait_group 0;" ::: "memory");
}
__device__ __forceinline__ void cp_wait1() {
    asm volatile("cp.async.wait_group 1;" ::: "memory");
}
__device__ __forceinline__ void ldsm4(uint32_t* r, uint32_t a) {
    asm volatile("ldmatrix.sync.aligned.m8n8.x4.shared.b16 {%0, %1, %2, %3}, [%4];"
                 : "=r"(r[0]), "=r"(r[1]), "=r"(r[2]), "=r"(r[3]) : "r"(a));
}
__device__ __forceinline__ void mma_bf16(float* c, const uint32_t* a, const uint32_t* b) {
    asm volatile(
        "mma.sync.aligned.m16n8k16.row.col.f32.bf16.bf16.f32 "
        "{%0, %1, %2, %3}, {%4, %5, %6, %7}, {%8, %9}, {%0, %1, %2, %3};"
        : "+f"(c[0]), "+f"(c[1]), "+f"(c[2]), "+f"(c[3])
        : "r"(a[0]), "r"(a[1]), "r"(a[2]), "r"(a[3]), "r"(b[0]), "r"(b[1]));
}

// ==================== HMMA GEMM ====================
// C[M,N] = (Ah+Al)[M,K] @ (Bh+Bl)[N,K]^T (+ D), fp32 out.
// CTA tile 128x128, BK=32, 8 warps (4m x 2n), warp tile 32x64.
// Requires M%128==0, K%32==0, N%8==0.
#define GSTRIDE 40                      // smem row stride in halves (32 + 8 pad)
#define GMAT (128 * GSTRIDE)            // halves per matrix
#define GSTAGE (4 * GMAT)               // halves per stage (Ah|Al|Bh|Bl)
#define GEMM_SMEM (2 * GSTAGE * 2)      // bytes (double buffered) = 81920

__global__ __launch_bounds__(256) void hmma_gemm(
    const bf16* __restrict__ Ah, const bf16* __restrict__ Al,
    const bf16* __restrict__ Bh, const bf16* __restrict__ Bl,
    const float* __restrict__ D, float* __restrict__ C,
    int M, int N, int K) {
    extern __shared__ __align__(128) bf16 sm[];

    const int tid = threadIdx.x;
    const int wid = tid >> 5;
    const int lane = tid & 31;
    const int row0 = blockIdx.y * 128;
    const int col0 = blockIdx.x * 128;
    const int m0w = (wid >> 1) * 32;    // warp m offset
    const int n0w = (wid & 1) * 64;     // warp n offset

    const uint32_t smb = smem_u32(sm);

    // ---- stage loader: 4 matrices x 128 rows x 32 halves, 16B chunks ----
    auto load_stage = [&](int s, int k0) {
        uint32_t sb = smb + s * GSTAGE * 2;
#pragma unroll
        for (int p = 0; p < 2; p++) {
            int idx = tid + p * 256;          // 0..511
            int r = idx >> 2;                 // row 0..127
            int ch = idx & 3;                 // 16B chunk
            int kk = k0 + ch * 8;
            uint32_t so = sb + (uint32_t)(r * GSTRIDE + ch * 8) * 2;
            // A hi/lo
            const bf16* gA = Ah + (size_t)(row0 + r) * K + kk;
            const bf16* gAl = Al + (size_t)(row0 + r) * K + kk;
            cp16(so, gA, 16);
            cp16(so + GMAT * 2, gAl, 16);
            // B hi/lo (guard N)
            int bn = col0 + r;
            int valid = (bn < N) ? 16 : 0;
            int bnc = (bn < N) ? bn : (N - 1);
            const bf16* gB = Bh + (size_t)bnc * K + kk;
            const bf16* gBl = Bl + (size_t)bnc * K + kk;
            cp16(so + 2 * GMAT * 2, gB, valid);
            cp16(so + 3 * GMAT * 2, gBl, valid);
        }
    };

    float acc[2][8][4];
#pragma unroll
    for (int mi = 0; mi < 2; mi++)
#pragma unroll
        for (int ni = 0; ni < 8; ni++)
#pragma unroll
            for (int j = 0; j < 4; j++) acc[mi][ni][j] = 0.f;

    const int NIT = K >> 5;
    load_stage(0, 0);
    cp_commit();

    // ldmatrix lane address components
    const int grp = lane >> 3, w = lane & 7;
    const int a_m = (grp & 1) * 8 + w;      // A: mat order m0k0,m8k0,m0k8,m8k8
    const int a_k = (grp >> 1) * 8;
    const int b_n = (grp >> 1) * 8 + w;     // B: mat order n0k0,n0k8,n8k0,n8k8
    const int b_k = (grp & 1) * 8;

    for (int it = 0; it < NIT; ++it) {
        int s = it & 1;
        if (it + 1 < NIT) {
            load_stage(s ^ 1, (it + 1) * 32);
            cp_commit();
            cp_wait1();
        } else {
            cp_wait0();
        }
        __syncthreads();

        uint32_t sb = smb + s * GSTAGE * 2;
#pragma unroll
        for (int ks = 0; ks < 2; ks++) {
            int k0 = ks * 16;
            uint32_t ahf[2][4], alf[2][4], bhf[8][2], blf[8][2];
#pragma unroll
            for (int mi = 0; mi < 2; mi++) {
                uint32_t addr = sb + (uint32_t)((m0w + mi * 16 + a_m) * GSTRIDE + k0 + a_k) * 2;
                ldsm4(ahf[mi], addr);
                ldsm4(alf[mi], addr + GMAT * 2);
            }
#pragma unroll
            for (int nb = 0; nb < 4; nb++) {
                uint32_t addr = sb + 2 * GMAT * 2 +
                                (uint32_t)((n0w + nb * 16 + b_n) * GSTRIDE + k0 + b_k) * 2;
                uint32_t t[4];
                ldsm4(t, addr);
                bhf[2 * nb][0] = t[0]; bhf[2 * nb][1] = t[1];
                bhf[2 * nb + 1][0] = t[2]; bhf[2 * nb + 1][1] = t[3];
                ldsm4(t, addr + GMAT * 2);
                blf[2 * nb][0] = t[0]; blf[2 * nb][1] = t[1];
                blf[2 * nb + 1][0] = t[2]; blf[2 * nb + 1][1] = t[3];
            }
#pragma unroll
            for (int mi = 0; mi < 2; mi++)
#pragma unroll
                for (int ni = 0; ni < 8; ni++) {
                    mma_bf16(acc[mi][ni], ahf[mi], bhf[ni]);
                    mma_bf16(acc[mi][ni], alf[mi], bhf[ni]);
                    mma_bf16(acc[mi][ni], ahf[mi], blf[ni]);
                }
        }
        __syncthreads();
    }

    // ---- epilogue ----
    const int qr = lane >> 2, qc = (lane & 3) * 2;
#pragma unroll
    for (int mi = 0; mi < 2; mi++) {
#pragma unroll
        for (int ni = 0; ni < 8; ni++) {
            int rr = row0 + m0w + mi * 16 + qr;
            int cc = col0 + n0w + ni * 8 + qc;
            if (cc < N) {
                float v0 = acc[mi][ni][0], v1 = acc[mi][ni][1];
                float v2 = acc[mi][ni][2], v3 = acc[mi][ni][3];
                size_t o0 = (size_t)rr * N + cc;
                size_t o1 = (size_t)(rr + 8) * N + cc;
                if (D) {
                    v0 += D[o0]; v1 += D[o0 + 1];
                    v2 += D[o1]; v3 += D[o1 + 1];
                }
                C[o0] = v0; C[o0 + 1] = v1;
                C[o1] = v2; C[o1 + 1] = v3;
            }
        }
    }
}

// ==================== weight transpose + bf16 split ====================
__global__ void wt_convert(const float* __restrict__ W, bf16* __restrict__ Bh,
                           bf16* __restrict__ Bl, int K, int N) {
    __shared__ float t[32][33];
    int k0 = blockIdx.x * 32, n0 = blockIdx.y * 32;
    for (int i = threadIdx.y; i < 32; i += 8)
        t[i][threadIdx.x] = W[(size_t)(k0 + i) * N + n0 + threadIdx.x];
    __syncthreads();
    for (int i = threadIdx.y; i < 32; i += 8) {
        float v = t[threadIdx.x][i];
        bf16 h = __float2bfloat16(v);
        size_t o = (size_t)(n0 + i) * K + k0 + threadIdx.x;
        Bh[o] = h;
        Bl[o] = __float2bfloat16(v - __bfloat162float(h));
    }
}

// ==================== RMSNorm -> bf16 hi/lo ====================
__global__ void rmsnorm_split(const float* __restrict__ in, const float* __restrict__ w,
                              bf16* __restrict__ oh, bf16* __restrict__ ol,
                              int cols, int in_ld) {
    int row = blockIdx.x;
    const float* x = in + (size_t)row * in_ld;
    float ss = 0.f;
    for (int c = threadIdx.x; c < cols; c += blockDim.x) {
        float v = x[c];
        ss += v * v;
    }
    __shared__ float red[256];
    red[threadIdx.x] = ss;
    __syncthreads();
    for (int s = 128; s > 0; s >>= 1) {
        if (threadIdx.x < s) red[threadIdx.x] += red[threadIdx.x + s];
        __syncthreads();
    }
    float scale = 1.0f / sqrtf(red[0] / (float)cols + 1e-5f);
    for (int c = threadIdx.x; c < cols; c += blockDim.x) {
        float v = x[c] * scale;
        if (w) v *= w[c];
        bf16 h = __float2bfloat16(v);
        size_t o = (size_t)row * cols + c;
        oh[o] = h;
        ol[o] = __float2bfloat16(v - __bfloat162float(h));
    }
}

// ==================== RoPE / assemble ====================
__global__ void rope_q_kernel(const float* __restrict__ qin,
                              const float* __restrict__ cosT, const float* __restrict__ sinT,
                              float* __restrict__ qout) {
    int t = blockIdx.x;
    int h = blockIdx.y;
    int s = t & (SEQLEN - 1);
    const float* in = qin + (size_t)t * (NH * DQK) + h * DQK;
    float* out = qout + (size_t)t * (NH * DQK) + h * DQK;
    int tid = threadIdx.x;
    if (tid < 32) {
        float xr = in[NOPE + 2 * tid];
        float xi = in[NOPE + 2 * tid + 1];
        float c = cosT[(size_t)s * 32 + tid];
        float sn = sinT[(size_t)s * 32 + tid];
        out[2 * tid] = xr * c - xi * sn;
        out[2 * tid + 1] = xr * sn + xi * c;
    }
    out[ROPE + tid] = in[tid];
}

__global__ void rope_k_kernel(const float* __restrict__ kvlr,
                              const float* __restrict__ cosT, const float* __restrict__ sinT,
                              float* __restrict__ krope) {
    int t = blockIdx.x;
    int s = t & (SEQLEN - 1);
    int j = threadIdx.x;
    const float* in = kvlr + (size_t)t * (KVLORA + ROPE) + KVLORA;
    float xr = in[2 * j];
    float xi = in[2 * j + 1];
    float c = cosT[(size_t)s * 32 + j];
    float sn = sinT[(size_t)s * 32 + j];
    krope[(size_t)t * ROPE + 2 * j] = xr * c - xi * sn;
    krope[(size_t)t * ROPE + 2 * j + 1] = xr * sn + xi * c;
}

__global__ void assemble_k_kernel(const float* __restrict__ krope, const float* __restrict__ kv,
                                  float* __restrict__ K) {
    int t = blockIdx.x;
    int h = blockIdx.y;
    int d = threadIdx.x;
    float v;
    if (d < ROPE)
        v = krope[(size_t)t * ROPE + d];
    else
        v = kv[(size_t)t * (NH * (NOPE + DV)) + h * NOPE + (d - ROPE)];
    K[(size_t)t * (NH * DQK) + h * DQK + d] = v;
}

// ==================== flash attention fp32, split-output ====================
#define ATT_QK_PAD 68
#define ATT_SMEM_FLOATS (192 * ATT_QK_PAD * 2 + 64 * 128 + 64 * 65 + 192)
#define ATT_SMEM_BYTES (ATT_SMEM_FLOATS * 4)

__global__ __launch_bounds__(256) void attn_kernel(
    const float* __restrict__ Q, const float* __restrict__ K,
    const float* __restrict__ KV, const int* __restrict__ seqmask,
    bf16* __restrict__ Oh, bf16* __restrict__ Ol) {
    extern __shared__ float smf[];
    float* QsT = smf;
    float* KsT = QsT + 192 * ATT_QK_PAD;
    float* Vs = KsT + 192 * ATT_QK_PAD;
    float* Ss = Vs + 64 * 128;
    float* mrow = Ss + 64 * 65;
    float* lrow = mrow + 64;
    float* crow = lrow + 64;

    const int tid = threadIdx.x;
    const int qt = gridDim.x - 1 - blockIdx.x;
    const int h = blockIdx.y;
    const int b = blockIdx.z;
    const int ty = tid >> 4, tx = tid & 15;
    const int r0 = ty * 4, c0 = tx * 4, cc0 = tx * 8;
    const float scale = 0.07216878364870323f;

    const float* Qb = Q + ((size_t)(b * SEQLEN + qt * 64) * NH + h) * DQK;
    for (int idx = tid; idx < 64 * 192; idx += 256) {
        int r = idx / 192, d = idx - r * 192;
        QsT[d * ATT_QK_PAD + r] = Qb[(size_t)r * (NH * DQK) + d];
    }
    if (tid < 64) {
        mrow[tid] = -INFINITY;
        lrow[tid] = 0.f;
    }
    float acc[4][8];
#pragma unroll
    for (int i = 0; i < 4; i++)
#pragma unroll
        for (int j = 0; j < 8; j++) acc[i][j] = 0.f;
    __syncthreads();

    for (int kt = 0; kt <= qt; kt++) {
        const float* Kb = K + ((size_t)(b * SEQLEN + kt * 64) * NH + h) * DQK;
        for (int idx = tid; idx < 64 * 192; idx += 256) {
            int r = idx / 192, d = idx - r * 192;
            KsT[d * ATT_QK_PAD + r] = Kb[(size_t)r * (NH * DQK) + d];
        }
        const float* Vb = KV + (size_t)(b * SEQLEN + kt * 64) * (NH * (NOPE + DV)) + NH * NOPE + h * DV;
        for (int idx = tid; idx < 64 * 128; idx += 256) {
            int r = idx >> 7, c = idx & 127;
            Vs[idx] = Vb[(size_t)r * (NH * (NOPE + DV)) + c];
        }
        __syncthreads();

        float s[4][4];
#pragma unroll
        for (int i = 0; i < 4; i++)
#pragma unroll
            for (int j = 0; j < 4; j++) s[i][j] = 0.f;

#pragma unroll 4
        for (int d = 0; d < 192; d++) {
            float4 qv = *(const float4*)&QsT[d * ATT_QK_PAD + r0];
            float4 kv4 = *(const float4*)&KsT[d * ATT_QK_PAD + c0];
            float qa[4] = {qv.x, qv.y, qv.z, qv.w};
            float ka[4] = {kv4.x, kv4.y, kv4.z, kv4.w};
#pragma unroll
            for (int i = 0; i < 4; i++)
#pragma unroll
                for (int j = 0; j < 4; j++) s[i][j] = fmaf(qa[i], ka[j], s[i][j]);
        }
#pragma unroll
        for (int j = 0; j < 4; j++) {
            int kg = kt * 64 + c0 + j;
            bool ok = seqmask[b * SEQLEN + kg] > 0;
#pragma unroll
            for (int i = 0; i < 4; i++) {
                int qg = qt * 64 + r0 + i;
                float v = s[i][j] * scale;
                if (kg > qg || !ok) v = -1e30f;
                Ss[(r0 + i) * 65 + c0 + j] = v;
            }
        }
        __syncthreads();

        if (tid < 64) {
            int r = tid;
            float mold = mrow[r];
            float mx = mold;
            for (int j = 0; j < 64; j++) mx = fmaxf(mx, Ss[r * 65 + j]);
            float corr = expf(mold - mx);
            float sum = 0.f;
            for (int j = 0; j < 64; j++) {
                float p = expf(Ss[r * 65 + j] - mx);
                Ss[r * 65 + j] = p;
                sum += p;
            }
            lrow[r] = lrow[r] * corr + sum;
            mrow[r] = mx;
            crow[r] = corr;
        }
        __syncthreads();

        float cf[4];
#pragma unroll
        for (int i = 0; i < 4; i++) cf[i] = crow[r0 + i];
#pragma unroll
        for (int i = 0; i < 4; i++)
#pragma unroll
            for (int j = 0; j < 8; j++) acc[i][j] *= cf[i];

        for (int k = 0; k < 64; k++) {
            float p[4];
#pragma unroll
            for (int i = 0; i < 4; i++) p[i] = Ss[(r0 + i) * 65 + k];
            float4 v0 = *(const float4*)&Vs[k * 128 + cc0];
            float4 v1 = *(const float4*)&Vs[k * 128 + cc0 + 4];
            float vv[8] = {v0.x, v0.y, v0.z, v0.w, v1.x, v1.y, v1.z, v1.w};
#pragma unroll
            for (int i = 0; i < 4; i++)
#pragma unroll
                for (int j = 0; j < 8; j++) acc[i][j] = fmaf(p[i], vv[j], acc[i][j]);
        }
        __syncthreads();
    }

    float inv[4];
#pragma unroll
    for (int i = 0; i < 4; i++) inv[i] = 1.f / lrow[r0 + i];
#pragma unroll
    for (int i = 0; i < 4; i++) {
        size_t base = (size_t)(b * SEQLEN + qt * 64 + r0 + i) * (NH * DV) + h * DV + cc0;
#pragma unroll
        for (int j = 0; j < 8; j++) {
            float v = acc[i][j] * inv[i];
            bf16 hh = __float2bfloat16(v);
            Oh[base + j] = hh;
            Ol[base + j] = __float2bfloat16(v - __bfloat162float(hh));
        }
    }
}

// ==================== silu(gate)*up -> bf16 hi/lo ====================
__global__ void silu_mul_split(const float* __restrict__ g, const float* __restrict__ u,
                               bf16* __restrict__ oh, bf16* __restrict__ ol, int n) {
    for (int i = blockIdx.x * blockDim.x + threadIdx.x; i < n; i += gridDim.x * blockDim.x) {
        float x = g[i];
        float v = (x / (1.f + expf(-x))) * u[i];
        bf16 h = __float2bfloat16(v);
        oh[i] = h;
        ol[i] = __float2bfloat16(v - __bfloat162float(h));
    }
}

// ==================== launch ====================
extern "C" void kernel_launch(void* const* d_in, const int* in_sizes, int n_in,
                              void* d_out, int out_size) {
    const float* hidden = (const float*)d_in[0];
    const int* seqmask = (const int*)d_in[1];
    const float* cosT = (const float*)d_in[2];
    const float* sinT = (const float*)d_in[3];
    const float* ln1 = (const float*)d_in[4];
    const float* ln2 = (const float*)d_in[5];
    const float* Wq_down = (const float*)d_in[6];
    const float* Wq_up = (const float*)d_in[7];
    const float* Wkv_down = (const float*)d_in[8];
    const float* Wkv_up = (const float*)d_in[9];
    const float* Wo = (const float*)d_in[10];
    const float* Wgate = (const float*)d_in[11];
    const float* Wup = (const float*)d_in[12];
    const float* Wdown = (const float*)d_in[13];
    float* out = (float*)d_out;

#define SYM(p, s) cudaGetSymbolAddress((void**)&p, s)
    float *p_qlat, *p_q, *p_Q, *p_kvlr, *p_kv, *p_krope, *p_K, *p_x, *p_gate, *p_up;
    SYM(p_qlat, g_qlat); SYM(p_q, g_q); SYM(p_Q, g_Q); SYM(p_kvlr, g_kvlr);
    SYM(p_kv, g_kv); SYM(p_krope, g_krope); SYM(p_K, g_K); SYM(p_x, g_x);
    SYM(p_gate, g_gate); SYM(p_up, g_up);

    bf16 *hh, *hl, *qlnh, *qlnl, *kvnh, *kvnl, *ath, *atl, *h2h, *h2l, *ffh, *ffl;
    SYM(hh, g_h_h); SYM(hl, g_h_l); SYM(qlnh, g_qln_h); SYM(qlnl, g_qln_l);
    SYM(kvnh, g_kvn_h); SYM(kvnl, g_kvn_l); SYM(ath, g_at_h); SYM(atl, g_at_l);
    SYM(h2h, g_h2_h); SYM(h2l, g_h2_l); SYM(ffh, g_ff_h); SYM(ffl, g_ff_l);

    bf16 *wqdh, *wqdl, *wquh, *wqul, *wkvdh, *wkvdl, *wkvuh, *wkvul;
    bf16 *woh, *wol, *wgh, *wgl, *wuh, *wul, *wdh, *wdl;
    SYM(wqdh, g_wqd_h); SYM(wqdl, g_wqd_l); SYM(wquh, g_wqu_h); SYM(wqul, g_wqu_l);
    SYM(wkvdh, g_wkvd_h); SYM(wkvdl, g_wkvd_l); SYM(wkvuh, g_wkvu_h); SYM(wkvul, g_wkvu_l);
    SYM(woh, g_wo_h); SYM(wol, g_wo_l); SYM(wgh, g_wg_h); SYM(wgl, g_wg_l);
    SYM(wuh, g_wu_h); SYM(wul, g_wu_l); SYM(wdh, g_wd_h); SYM(wdl, g_wd_l);
#undef SYM

    cudaFuncSetAttribute(hmma_gemm, cudaFuncAttributeMaxDynamicSharedMemorySize, GEMM_SMEM);
    cudaFuncSetAttribute(attn_kernel, cudaFuncAttributeMaxDynamicSharedMemorySize, ATT_SMEM_BYTES);

    dim3 tb(32, 8);
    // weight conversions (transpose + hi/lo split)
    wt_convert<<<dim3(DM / 32, QLORA / 32), tb>>>(Wq_down, wqdh, wqdl, DM, QLORA);
    wt_convert<<<dim3(QLORA / 32, (NH * DQK) / 32), tb>>>(Wq_up, wquh, wqul, QLORA, NH * DQK);
    wt_convert<<<dim3(DM / 32, (KVLORA + ROPE) / 32), tb>>>(Wkv_down, wkvdh, wkvdl, DM, KVLORA + ROPE);
    wt_convert<<<dim3(KVLORA / 32, (NH * (NOPE + DV)) / 32), tb>>>(Wkv_up, wkvuh, wkvul, KVLORA, NH * (NOPE + DV));
    wt_convert<<<dim3((NH * DV) / 32, DM / 32), tb>>>(Wo, woh, wol, NH * DV, DM);
    wt_convert<<<dim3(DM / 32, DFF / 32), tb>>>(Wgate, wgh, wgl, DM, DFF);
    wt_convert<<<dim3(DM / 32, DFF / 32), tb>>>(Wup, wuh, wul, DM, DFF);
    wt_convert<<<dim3(DFF / 32, DM / 32), tb>>>(Wdown, wdh, wdl, DFF, DM);

    // 1. h = rmsnorm(hidden) * ln1
    rmsnorm_split<<<TOKENS, 256>>>(hidden, ln1, hh, hl, DM, DM);

    // 2. q_latent = rmsnorm(h @ Wq_down)
    hmma_gemm<<<dim3(QLORA / 128, TOKENS / 128), 256, GEMM_SMEM>>>(hh, hl, wqdh, wqdl, nullptr, p_qlat,
                                                                   TOKENS, QLORA, DM);
    rmsnorm_split<<<TOKENS, 256>>>(p_qlat, nullptr, qlnh, qlnl, QLORA, QLORA);

    // 3. q = q_latent @ Wq_up ; rope
    hmma_gemm<<<dim3((NH * DQK) / 128, TOKENS / 128), 256, GEMM_SMEM>>>(qlnh, qlnl, wquh, wqul, nullptr, p_q,
                                                                        TOKENS, NH * DQK, QLORA);
    rope_q_kernel<<<dim3(TOKENS, NH), 128>>>(p_q, cosT, sinT, p_Q);

    // 4. kv_lr = h @ Wkv_down
    hmma_gemm<<<dim3((KVLORA + ROPE + 127) / 128, TOKENS / 128), 256, GEMM_SMEM>>>(
        hh, hl, wkvdh, wkvdl, nullptr, p_kvlr, TOKENS, KVLORA + ROPE, DM);
    rope_k_kernel<<<TOKENS, 32>>>(p_kvlr, cosT, sinT, p_krope);
    rmsnorm_split<<<TOKENS, 256>>>(p_kvlr, nullptr, kvnh, kvnl, KVLORA, KVLORA + ROPE);

    // 5. kv = kvnorm @ Wkv_up ; assemble K
    hmma_gemm<<<dim3((NH * (NOPE + DV)) / 128, TOKENS / 128), 256, GEMM_SMEM>>>(
        kvnh, kvnl, wkvuh, wkvul, nullptr, p_kv, TOKENS, NH * (NOPE + DV), KVLORA);
    assemble_k_kernel<<<dim3(TOKENS, NH), 192>>>(p_krope, p_kv, p_K);

    // 6. attention -> bf16 hi/lo
    attn_kernel<<<dim3(SEQLEN / 64, NH, NB), 256, ATT_SMEM_BYTES>>>(p_Q, p_K, p_kv, seqmask, ath, atl);

    // 7. x = hidden + attn @ Wo
    hmma_gemm<<<dim3(DM / 128, TOKENS / 128), 256, GEMM_SMEM>>>(ath, atl, woh, wol, hidden, p_x,
                                                                TOKENS, DM, NH * DV);

    // 8. h2 = rmsnorm(x) * ln2
    rmsnorm_split<<<TOKENS, 256>>>(p_x, ln2, h2h, h2l, DM, DM);

    // 9. MLP
    hmma_gemm<<<dim3(DFF / 128, TOKENS / 128), 256, GEMM_SMEM>>>(h2h, h2l, wgh, wgl, nullptr, p_gate,
                                                                 TOKENS, DFF, DM);
    hmma_gemm<<<dim3(DFF / 128, TOKENS / 128), 256, GEMM_SMEM>>>(h2h, h2l, wuh, wul, nullptr, p_up,
                                                                 TOKENS, DFF, DM);
    silu_mul_split<<<8192, 256>>>(p_gate, p_up, ffh, ffl, TOKENS * DFF);

    // 10. out = x + ff @ Wdown
    hmma_gemm<<<dim3(DM / 128, TOKENS / 128), 256, GEMM_SMEM>>>(ffh, ffl, wdh, wdl, p_x, out,
                                                                TOKENS, DM, DFF);
}